// round 6
// baseline (speedup 1.0000x reference)
#include <cuda_runtime.h>
#include <cuda_bf16.h>
#include <cstdint>

// Problem shapes (fixed for this dataset)
#define TOKENS 8192
#define DIN    4096
#define DOUT   4096

// GEMM tiling (int8 path, baseline PTX only: cp.async + ldmatrix + mma.sync)
#define BM 128
#define BN 256
#define BK 128                       // 128 int8 = one 128B SW128 row
#define STAGES 3
#define NIT (DIN / BK)               // 32 K-iterations

#define A_BYTES (BM * BK)            // 16384
#define B_BYTES (BN * BK)            // 32768
#define STAGE_BYTES (A_BYTES + B_BYTES)  // 49152

// SMEM layout (dynamic)
#define SM_SW   0                    // 256 floats
#define SM_BIAS 1024                 // 256 floats
#define SM_ST0  2048
#define SMEM_TOTAL (SM_ST0 + STAGES * STAGE_BYTES)   // 149504

// ---------------- device-global scratch (no allocation allowed) ----------------
__device__ __align__(256) int8_t g_qx[(size_t)TOKENS * DIN];
__device__ __align__(256) int8_t g_qw[(size_t)DOUT * DIN];
__device__ float g_sx[TOKENS];
__device__ float g_sw[DOUT];

// ---------------- PTX helpers (all baseline, compile under compute_103) --------
__device__ __forceinline__ uint32_t smem_u32(const void* p) {
    uint32_t a;
    asm("{ .reg .u64 t; cvta.to.shared.u64 t, %1; cvt.u32.u64 %0, t; }" : "=r"(a) : "l"(p));
    return a;
}

#define CP16(dst, src) \
    asm volatile("cp.async.cg.shared.global [%0], [%1], 16;\n" \
                 :: "r"(dst), "l"(__cvta_generic_to_global(src)))
#define CP_COMMIT() asm volatile("cp.async.commit_group;\n" ::: "memory")
#define CP_WAIT1()  asm volatile("cp.async.wait_group 1;\n" ::: "memory")

#define LDSM4(r, addr) \
    asm volatile("ldmatrix.sync.aligned.m8n8.x4.shared.b16 {%0,%1,%2,%3}, [%4];" \
                 : "=r"((r)[0]), "=r"((r)[1]), "=r"((r)[2]), "=r"((r)[3]) : "r"(addr))
#define LDSM2(r, addr) \
    asm volatile("ldmatrix.sync.aligned.m8n8.x2.shared.b16 {%0,%1}, [%2];" \
                 : "=r"((r)[0]), "=r"((r)[1]) : "r"(addr))

#define IMMA(d, a, b) \
    asm volatile("mma.sync.aligned.m16n8k32.row.col.s32.s8.s8.s32 " \
                 "{%0,%1,%2,%3}, {%4,%5,%6,%7}, {%8,%9}, {%0,%1,%2,%3};" \
                 : "+r"((d)[0]), "+r"((d)[1]), "+r"((d)[2]), "+r"((d)[3]) \
                 : "r"((a)[0]), "r"((a)[1]), "r"((a)[2]), "r"((a)[3]), \
                   "r"((b)[0]), "r"((b)[1]))

// ---------------- quantize: per-row absmax -> int8 values + fp32 scale ---------
// 256 threads/row; thread t owns 16 consecutive floats at t*16.
__global__ void __launch_bounds__(256) quant_kernel(const float* __restrict__ in, int which) {
    const int row = blockIdx.x;
    const int tid = threadIdx.x;
    const float4* inr = reinterpret_cast<const float4*>(in + (size_t)row * DIN) + tid * 4;

    float4 v[4];
    float amax = 0.f;
#pragma unroll
    for (int i = 0; i < 4; i++) {
        v[i] = inr[i];
        amax = fmaxf(amax, fmaxf(fmaxf(fabsf(v[i].x), fabsf(v[i].y)),
                                 fmaxf(fabsf(v[i].z), fabsf(v[i].w))));
    }
#pragma unroll
    for (int o = 16; o; o >>= 1) amax = fmaxf(amax, __shfl_xor_sync(0xffffffffu, amax, o));

    __shared__ float red[8];
    __shared__ float s_bcast;
    if ((tid & 31) == 0) red[tid >> 5] = amax;
    __syncthreads();
    if (tid < 8) {
        float a = red[tid];
#pragma unroll
        for (int o = 4; o; o >>= 1) a = fmaxf(a, __shfl_xor_sync(0xffu, a, o));
        // IEEE ops to bit-match jnp: max(absmax,1e-8)/127
        if (tid == 0) s_bcast = __fdiv_rn(fmaxf(a, 1e-8f), 127.0f);
    }
    __syncthreads();
    const float s = s_bcast;

    int8_t* q = which ? g_qw : g_qx;
    float* sc = which ? g_sw : g_sx;
    if (tid == 0) sc[row] = s;

    uint32_t packed[4];
#pragma unroll
    for (int i = 0; i < 4; i++) {
        float4 t = v[i];
        // __fdiv_rn + rintf (round-half-even) matches jnp.round(a/scale) exactly
        int q0 = (int)fminf(fmaxf(rintf(__fdiv_rn(t.x, s)), -127.f), 127.f);
        int q1 = (int)fminf(fmaxf(rintf(__fdiv_rn(t.y, s)), -127.f), 127.f);
        int q2 = (int)fminf(fmaxf(rintf(__fdiv_rn(t.z, s)), -127.f), 127.f);
        int q3 = (int)fminf(fmaxf(rintf(__fdiv_rn(t.w, s)), -127.f), 127.f);
        packed[i] = (q0 & 255) | ((q1 & 255) << 8) | ((q2 & 255) << 16) | ((q3 & 255) << 24);
    }
    uint4* qp = reinterpret_cast<uint4*>(q + (size_t)row * DIN);
    qp[tid] = make_uint4(packed[0], packed[1], packed[2], packed[3]);
}

// ---------------- GEMM: out[t,o] = (qx . qw) * sx[t]*sw[o] + bias[o] -----------
// 8 warps as 2(m) x 4(n); warp tile 64x64; mma m16n8k32 s8.
__global__ void __launch_bounds__(256, 1)
gemm_kernel(const float* __restrict__ bias, float* __restrict__ out) {
    extern __shared__ char smem[];
    const uint32_t sb = smem_u32(smem);
    const int tid = threadIdx.x;
    const int wid = tid >> 5;
    const int L   = tid & 31;
    const int bm  = blockIdx.x;   // 64
    const int bn  = blockIdx.y;   // 16

    // stage dequant vectors for this BN slab
    ((float*)(smem + SM_SW))[tid]   = g_sw[bn * BN + tid];
    ((float*)(smem + SM_BIAS))[tid] = bias[bn * BN + tid];

    const int8_t* gA = g_qx + (size_t)bm * BM * DIN;
    const int8_t* gB = g_qw + (size_t)bn * BN * DIN;

    // per-stage fill: A 4 chunks/thread, B 8 chunks/thread (16B each)
    auto load_stage = [&](int kt, int slot) {
        uint32_t ab = sb + SM_ST0 + slot * STAGE_BYTES;
        uint32_t bb = ab + A_BYTES;
        const int8_t* aT = gA + kt * BK;
        const int8_t* bT = gB + kt * BK;
#pragma unroll
        for (int i = 0; i < 4; i++) {
            int c = tid + i * 256;
            int row = c >> 3, ko = c & 7;
            uint32_t off = row * 128 + ((ko * 16) ^ ((row & 7) * 16));   // SW128
            CP16(ab + off, aT + (size_t)row * DIN + ko * 16);
        }
#pragma unroll
        for (int i = 0; i < 8; i++) {
            int c = tid + i * 256;
            int row = c >> 3, ko = c & 7;
            uint32_t off = row * 128 + ((ko * 16) ^ ((row & 7) * 16));
            CP16(bb + off, bT + (size_t)row * DIN + ko * 16);
        }
    };

    // warp layout + per-lane ldmatrix address constants
    const int wm = wid >> 2;             // 0..1 -> 64 M rows
    const int wn = wid & 3;              // 0..3 -> 64 N cols
    const int lr = L & 7;
    const int cRow = lr * 16;            // swizzle XOR term ((row&7)*16), same for A and B
    const int akh = ((L >> 4) & 1) * 16; // A k-half select (matrices 2,3)
    const int bkh = ((L >> 3) & 1) * 16; // B k-half select (matrix 1)

    uint32_t aRow[4], bRow[8];
#pragma unroll
    for (int mf = 0; mf < 4; mf++)
        aRow[mf] = (uint32_t)(wm * 64 + mf * 16 + lr + ((L >> 3) & 1) * 8) * 128;
#pragma unroll
    for (int nf = 0; nf < 8; nf++)
        bRow[nf] = (uint32_t)(wn * 64 + nf * 8 + lr) * 128;

    int acc[4][8][4];
#pragma unroll
    for (int mf = 0; mf < 4; mf++)
#pragma unroll
        for (int nf = 0; nf < 8; nf++)
#pragma unroll
            for (int j = 0; j < 4; j++) acc[mf][nf][j] = 0;

    // prologue: fill stages 0..STAGES-2
#pragma unroll
    for (int p = 0; p < STAGES - 1; ++p) {
        load_stage(p, p);
        CP_COMMIT();
    }

#pragma unroll 1
    for (int it = 0; it < NIT; ++it) {
        CP_WAIT1();          // stage `it` resident (newest committed group = it+1)
        __syncthreads();     // all warps done with compute(it-1) before its slot refills

        const int jf = it + STAGES - 1;
        if (jf < NIT) load_stage(jf, jf % STAGES);
        CP_COMMIT();         // uniform group count (empty near tail)

        const uint32_t ab = sb + SM_ST0 + (it % STAGES) * STAGE_BYTES;
        const uint32_t bb = ab + A_BYTES;

#pragma unroll
        for (int ks = 0; ks < 4; ks++) {
            const int kb = ks * 32;
            uint32_t a[4][4], b[8][2];
#pragma unroll
            for (int mf = 0; mf < 4; mf++)
                LDSM4(a[mf], ab + aRow[mf] + ((kb + akh) ^ cRow));
#pragma unroll
            for (int nf = 0; nf < 8; nf++)
                LDSM2(b[nf], bb + bRow[nf] + ((kb + bkh) ^ cRow));
#pragma unroll
            for (int mf = 0; mf < 4; mf++)
#pragma unroll
                for (int nf = 0; nf < 8; nf++)
                    IMMA(acc[mf][nf], a[mf], b[nf]);
        }
    }

    // epilogue: dequant + bias, direct float2 stores
    const int qid = L >> 2;
    const int tc  = (L & 3) * 2;
    const float* swp = (const float*)(smem + SM_SW);
    const float* bp  = (const float*)(smem + SM_BIAS);

#pragma unroll
    for (int mf = 0; mf < 4; mf++) {
        const size_t gr0 = (size_t)bm * BM + wm * 64 + mf * 16 + qid;
        const float sx0 = g_sx[gr0];
        const float sx1 = g_sx[gr0 + 8];
        float* o0 = out + gr0 * DOUT + bn * BN;
        float* o1 = o0 + (size_t)8 * DOUT;
#pragma unroll
        for (int nf = 0; nf < 8; nf++) {
            const int col = wn * 64 + nf * 8 + tc;
            const float w0 = swp[col], w1 = swp[col + 1];
            const float b0 = bp[col],  b1 = bp[col + 1];
            float2 v0, v1;
            v0.x = (float)acc[mf][nf][0] * (sx0 * w0) + b0;
            v0.y = (float)acc[mf][nf][1] * (sx0 * w1) + b1;
            v1.x = (float)acc[mf][nf][2] * (sx1 * w0) + b0;
            v1.y = (float)acc[mf][nf][3] * (sx1 * w1) + b1;
            *reinterpret_cast<float2*>(o0 + col) = v0;
            *reinterpret_cast<float2*>(o1 + col) = v1;
        }
    }
}

// ---------------- launch ----------------
extern "C" void kernel_launch(void* const* d_in, const int* in_sizes, int n_in,
                              void* d_out, int out_size) {
    const float* x    = (const float*)d_in[0];
    const float* W    = (const float*)d_in[1];
    const float* bias = (const float*)d_in[2];
    float* out        = (float*)d_out;

    quant_kernel<<<TOKENS, 256>>>(x, 0);
    quant_kernel<<<DOUT, 256>>>(W, 1);

    cudaFuncSetAttribute(gemm_kernel, cudaFuncAttributeMaxDynamicSharedMemorySize, SMEM_TOTAL);
    dim3 grid(TOKENS / BM, DOUT / BN);
    gemm_kernel<<<grid, 256, SMEM_TOTAL>>>(bias, out);
}

// round 7
// speedup vs baseline: 2.6879x; 2.6879x over previous
#include <cuda_runtime.h>
#include <cuda_bf16.h>
#include <cstdint>

// Problem shapes (fixed for this dataset)
#define TOKENS 8192
#define DIN    4096
#define DOUT   4096

// GEMM tiling (bf16 HMMA path, baseline PTX only: cp.async + ldmatrix + mma.sync)
#define BM 128
#define BN 256
#define BK 64                        // 64 bf16 = one 128B SW128 row
#define STAGES 3
#define NIT (DIN / BK)               // 64 K-iterations

#define A_BYTES (BM * 128)           // 16384
#define B_BYTES (BN * 128)           // 32768
#define STAGE_BYTES (A_BYTES + B_BYTES)  // 49152

// SMEM layout (dynamic)
#define SM_SW   0                    // 256 floats
#define SM_BIAS 1024                 // 256 floats
#define SM_ST0  2048
#define SMEM_TOTAL (SM_ST0 + STAGES * STAGE_BYTES)   // 149504

// ---------------- device-global scratch (no allocation allowed) ----------------
__device__ __align__(256) __nv_bfloat16 g_qx[(size_t)TOKENS * DIN];
__device__ __align__(256) __nv_bfloat16 g_qw[(size_t)DOUT * DIN];
__device__ float g_sx[TOKENS];
__device__ float g_sw[DOUT];

// ---------------- PTX helpers (all baseline, compile under compute_103) --------
__device__ __forceinline__ uint32_t smem_u32(const void* p) {
    uint32_t a;
    asm("{ .reg .u64 t; cvta.to.shared.u64 t, %1; cvt.u32.u64 %0, t; }" : "=r"(a) : "l"(p));
    return a;
}

#define CP16(dst, src) \
    asm volatile("cp.async.cg.shared.global [%0], [%1], 16;\n" \
                 :: "r"(dst), "l"(__cvta_generic_to_global(src)))
#define CP_COMMIT() asm volatile("cp.async.commit_group;\n" ::: "memory")
#define CP_WAIT1()  asm volatile("cp.async.wait_group 1;\n" ::: "memory")

#define LDSM4(r, addr) \
    asm volatile("ldmatrix.sync.aligned.m8n8.x4.shared.b16 {%0,%1,%2,%3}, [%4];" \
                 : "=r"((r)[0]), "=r"((r)[1]), "=r"((r)[2]), "=r"((r)[3]) : "r"(addr))
#define LDSM2(r, addr) \
    asm volatile("ldmatrix.sync.aligned.m8n8.x2.shared.b16 {%0,%1}, [%2];" \
                 : "=r"((r)[0]), "=r"((r)[1]) : "r"(addr))

// bf16 x bf16 -> f32 accumulate (HMMA hardware fallback path on sm_103)
#define HMMA(d, a, b) \
    asm volatile("mma.sync.aligned.m16n8k16.row.col.f32.bf16.bf16.f32 " \
                 "{%0,%1,%2,%3}, {%4,%5,%6,%7}, {%8,%9}, {%0,%1,%2,%3};" \
                 : "+f"((d)[0]), "+f"((d)[1]), "+f"((d)[2]), "+f"((d)[3]) \
                 : "r"((a)[0]), "r"((a)[1]), "r"((a)[2]), "r"((a)[3]), \
                   "r"((b)[0]), "r"((b)[1]))

// ---------------- quantize: per-row absmax -> bf16 int values + fp32 scale -----
// 256 threads/row; thread t owns 16 consecutive floats at t*16.
__global__ void __launch_bounds__(256) quant_kernel(const float* __restrict__ in, int which) {
    const int row = blockIdx.x;
    const int tid = threadIdx.x;
    const float4* inr = reinterpret_cast<const float4*>(in + (size_t)row * DIN) + tid * 4;

    float4 v[4];
    float amax = 0.f;
#pragma unroll
    for (int i = 0; i < 4; i++) {
        v[i] = inr[i];
        amax = fmaxf(amax, fmaxf(fmaxf(fabsf(v[i].x), fabsf(v[i].y)),
                                 fmaxf(fabsf(v[i].z), fabsf(v[i].w))));
    }
#pragma unroll
    for (int o = 16; o; o >>= 1) amax = fmaxf(amax, __shfl_xor_sync(0xffffffffu, amax, o));

    __shared__ float red[8];
    __shared__ float s_bcast;
    if ((tid & 31) == 0) red[tid >> 5] = amax;
    __syncthreads();
    if (tid < 8) {
        float a = red[tid];
#pragma unroll
        for (int o = 4; o; o >>= 1) a = fmaxf(a, __shfl_xor_sync(0xffu, a, o));
        // IEEE ops to bit-match jnp: max(absmax,1e-8)/127
        if (tid == 0) s_bcast = __fdiv_rn(fmaxf(a, 1e-8f), 127.0f);
    }
    __syncthreads();
    const float s = s_bcast;

    __nv_bfloat16* q = which ? g_qw : g_qx;
    float* sc = which ? g_sw : g_sx;
    if (tid == 0) sc[row] = s;

    // quantized values are integers in [-127,127]: exact in bf16
    __nv_bfloat162* qp = reinterpret_cast<__nv_bfloat162*>(q + (size_t)row * DIN);
#pragma unroll
    for (int i = 0; i < 4; i++) {
        float4 t = v[i];
        // __fdiv_rn + rintf (round-half-even) matches jnp.round(a/scale) exactly
        float q0 = fminf(fmaxf(rintf(__fdiv_rn(t.x, s)), -127.f), 127.f);
        float q1 = fminf(fmaxf(rintf(__fdiv_rn(t.y, s)), -127.f), 127.f);
        float q2 = fminf(fmaxf(rintf(__fdiv_rn(t.z, s)), -127.f), 127.f);
        float q3 = fminf(fmaxf(rintf(__fdiv_rn(t.w, s)), -127.f), 127.f);
        const int p = tid * 8 + i * 2;
        qp[p]     = __floats2bfloat162_rn(q0, q1);
        qp[p + 1] = __floats2bfloat162_rn(q2, q3);
    }
}

// ---------------- GEMM: out[t,o] = (qx . qw) * sx[t]*sw[o] + bias[o] -----------
// 8 warps as 2(m) x 4(n); warp tile 64x64; mma m16n8k16 bf16 -> f32.
__global__ void __launch_bounds__(256, 1)
gemm_kernel(const float* __restrict__ bias, float* __restrict__ out) {
    extern __shared__ char smem[];
    const uint32_t sb = smem_u32(smem);
    const int tid = threadIdx.x;
    const int wid = tid >> 5;
    const int L   = tid & 31;
    const int bm  = blockIdx.x;   // 64
    const int bn  = blockIdx.y;   // 16

    // stage dequant vectors for this BN slab
    ((float*)(smem + SM_SW))[tid]   = g_sw[bn * BN + tid];
    ((float*)(smem + SM_BIAS))[tid] = bias[bn * BN + tid];

    const __nv_bfloat16* gA = g_qx + (size_t)bm * BM * DIN;
    const __nv_bfloat16* gB = g_qw + (size_t)bn * BN * DIN;

    // per-stage fill: A 4 chunks/thread, B 8 chunks/thread (16B each)
    auto load_stage = [&](int kt, int slot) {
        uint32_t ab = sb + SM_ST0 + slot * STAGE_BYTES;
        uint32_t bb = ab + A_BYTES;
        const __nv_bfloat16* aT = gA + kt * BK;
        const __nv_bfloat16* bT = gB + kt * BK;
#pragma unroll
        for (int i = 0; i < 4; i++) {
            int c = tid + i * 256;
            int row = c >> 3, ko = c & 7;
            uint32_t off = row * 128 + ((ko * 16) ^ ((row & 7) * 16));   // SW128
            CP16(ab + off, aT + (size_t)row * DIN + ko * 8);
        }
#pragma unroll
        for (int i = 0; i < 8; i++) {
            int c = tid + i * 256;
            int row = c >> 3, ko = c & 7;
            uint32_t off = row * 128 + ((ko * 16) ^ ((row & 7) * 16));
            CP16(bb + off, bT + (size_t)row * DIN + ko * 8);
        }
    };

    // warp layout + per-lane ldmatrix address constants
    const int wm = wid >> 2;             // 0..1 -> 64 M rows
    const int wn = wid & 3;              // 0..3 -> 64 N cols
    const int lr = L & 7;
    const int cRow = lr * 16;            // swizzle XOR term ((row&7)*16)
    const int akh = ((L >> 4) & 1) * 16; // A k-half select (matrices 2,3)
    const int bkh = ((L >> 3) & 1) * 16; // B k-half select (matrix 1)

    uint32_t aRow[4], bRow[8];
#pragma unroll
    for (int mf = 0; mf < 4; mf++)
        aRow[mf] = (uint32_t)(wm * 64 + mf * 16 + lr + ((L >> 3) & 1) * 8) * 128;
#pragma unroll
    for (int nf = 0; nf < 8; nf++)
        bRow[nf] = (uint32_t)(wn * 64 + nf * 8 + lr) * 128;

    float acc[4][8][4];
#pragma unroll
    for (int mf = 0; mf < 4; mf++)
#pragma unroll
        for (int nf = 0; nf < 8; nf++)
#pragma unroll
            for (int j = 0; j < 4; j++) acc[mf][nf][j] = 0.f;

    // prologue: fill stages 0..STAGES-2
#pragma unroll
    for (int p = 0; p < STAGES - 1; ++p) {
        load_stage(p, p);
        CP_COMMIT();
    }

#pragma unroll 1
    for (int it = 0; it < NIT; ++it) {
        CP_WAIT1();          // stage `it` resident
        __syncthreads();     // all warps done with compute(it-1) before its slot refills

        const int jf = it + STAGES - 1;
        if (jf < NIT) load_stage(jf, jf % STAGES);
        CP_COMMIT();         // uniform group count (empty near tail)

        const uint32_t ab = sb + SM_ST0 + (it % STAGES) * STAGE_BYTES;
        const uint32_t bb = ab + A_BYTES;

#pragma unroll
        for (int ks = 0; ks < 4; ks++) {
            const int kb = ks * 32;      // k16 bf16 = 32 bytes
            uint32_t a[4][4], b[8][2];
#pragma unroll
            for (int mf = 0; mf < 4; mf++)
                LDSM4(a[mf], ab + aRow[mf] + ((kb + akh) ^ cRow));
#pragma unroll
            for (int nf = 0; nf < 8; nf++)
                LDSM2(b[nf], bb + bRow[nf] + ((kb + bkh) ^ cRow));
#pragma unroll
            for (int mf = 0; mf < 4; mf++)
#pragma unroll
                for (int nf = 0; nf < 8; nf++)
                    HMMA(acc[mf][nf], a[mf], b[nf]);
        }
    }

    // epilogue: dequant + bias, direct float2 stores
    const int qid = L >> 2;
    const int tc  = (L & 3) * 2;
    const float* swp = (const float*)(smem + SM_SW);
    const float* bp  = (const float*)(smem + SM_BIAS);

#pragma unroll
    for (int mf = 0; mf < 4; mf++) {
        const size_t gr0 = (size_t)bm * BM + wm * 64 + mf * 16 + qid;
        const float sx0 = g_sx[gr0];
        const float sx1 = g_sx[gr0 + 8];
        float* o0 = out + gr0 * DOUT + bn * BN;
        float* o1 = o0 + (size_t)8 * DOUT;
#pragma unroll
        for (int nf = 0; nf < 8; nf++) {
            const int col = wn * 64 + nf * 8 + tc;
            const float w0 = swp[col], w1 = swp[col + 1];
            const float b0 = bp[col],  b1 = bp[col + 1];
            float2 v0, v1;
            v0.x = acc[mf][nf][0] * (sx0 * w0) + b0;
            v0.y = acc[mf][nf][1] * (sx0 * w1) + b1;
            v1.x = acc[mf][nf][2] * (sx1 * w0) + b0;
            v1.y = acc[mf][nf][3] * (sx1 * w1) + b1;
            *reinterpret_cast<float2*>(o0 + col) = v0;
            *reinterpret_cast<float2*>(o1 + col) = v1;
        }
    }
}

// ---------------- launch ----------------
extern "C" void kernel_launch(void* const* d_in, const int* in_sizes, int n_in,
                              void* d_out, int out_size) {
    const float* x    = (const float*)d_in[0];
    const float* W    = (const float*)d_in[1];
    const float* bias = (const float*)d_in[2];
    float* out        = (float*)d_out;

    quant_kernel<<<TOKENS, 256>>>(x, 0);
    quant_kernel<<<DOUT, 256>>>(W, 1);

    cudaFuncSetAttribute(gemm_kernel, cudaFuncAttributeMaxDynamicSharedMemorySize, SMEM_TOTAL);
    dim3 grid(TOKENS / BM, DOUT / BN);
    gemm_kernel<<<grid, 256, SMEM_TOTAL>>>(bias, out);
}

// round 9
// speedup vs baseline: 2.7335x; 1.0170x over previous
#include <cuda_runtime.h>
#include <cuda_bf16.h>
#include <cstdint>

// Problem shapes (fixed for this dataset)
#define TOKENS 8192
#define DIN    4096
#define DOUT   4096

// GEMM tiling (bf16 HMMA path, baseline PTX only: cp.async + ldmatrix + mma.sync)
#define BM 128
#define BN 256
#define BK 64                        // 64 bf16 = one 128B SW128 row
#define STAGES 3
#define NIT (DIN / BK)               // 64 K-iterations

#define A_BYTES (BM * 128)           // 16384
#define B_BYTES (BN * 128)           // 32768
#define STAGE_BYTES (A_BYTES + B_BYTES)  // 49152

// SMEM layout (dynamic)
#define SM_SW   0                    // 256 floats
#define SM_BIAS 1024                 // 256 floats
#define SM_ST0  2048
#define SMEM_TOTAL (SM_ST0 + STAGES * STAGE_BYTES)   // 149504

// ---------------- device-global scratch (no allocation allowed) ----------------
__device__ __align__(256) __nv_bfloat16 g_qx[(size_t)TOKENS * DIN];
__device__ __align__(256) __nv_bfloat16 g_qw[(size_t)DOUT * DIN];
__device__ float g_sx[TOKENS];
__device__ float g_sw[DOUT];

// ---------------- PTX helpers (all baseline, compile under compute_103) --------
__device__ __forceinline__ uint32_t smem_u32(const void* p) {
    uint32_t a;
    asm("{ .reg .u64 t; cvta.to.shared.u64 t, %1; cvt.u32.u64 %0, t; }" : "=r"(a) : "l"(p));
    return a;
}

#define CP16(dst, src) \
    asm volatile("cp.async.cg.shared.global [%0], [%1], 16;\n" \
                 :: "r"(dst), "l"(__cvta_generic_to_global(src)))
#define CP_COMMIT() asm volatile("cp.async.commit_group;\n" ::: "memory")
#define CP_WAIT1()  asm volatile("cp.async.wait_group 1;\n" ::: "memory")

#define LDSM4(r, addr) \
    asm volatile("ldmatrix.sync.aligned.m8n8.x4.shared.b16 {%0,%1,%2,%3}, [%4];" \
                 : "=r"((r)[0]), "=r"((r)[1]), "=r"((r)[2]), "=r"((r)[3]) : "r"(addr))

// bf16 x bf16 -> f32 accumulate (HMMA hardware fallback path on sm_103)
#define HMMA(d, a, b0, b1) \
    asm volatile("mma.sync.aligned.m16n8k16.row.col.f32.bf16.bf16.f32 " \
                 "{%0,%1,%2,%3}, {%4,%5,%6,%7}, {%8,%9}, {%0,%1,%2,%3};" \
                 : "+f"((d)[0]), "+f"((d)[1]), "+f"((d)[2]), "+f"((d)[3]) \
                 : "r"((a)[0]), "r"((a)[1]), "r"((a)[2]), "r"((a)[3]), \
                   "r"(b0), "r"(b1))

// ---------------- quantize (fused x + W): per-row absmax -> bf16 ints + scale --
// grid = TOKENS + DOUT; 256 threads/row; thread t owns 16 consecutive floats.
__global__ void __launch_bounds__(256) quant_kernel(const float* __restrict__ x,
                                                    const float* __restrict__ W) {
    const int blk = blockIdx.x;
    const bool isW = (blk >= TOKENS);
    const int row = isW ? (blk - TOKENS) : blk;
    const float* in = isW ? W : x;
    const int tid = threadIdx.x;
    const float4* inr = reinterpret_cast<const float4*>(in + (size_t)row * DIN) + tid * 4;

    float4 v[4];
    float amax = 0.f;
#pragma unroll
    for (int i = 0; i < 4; i++) {
        v[i] = inr[i];
        amax = fmaxf(amax, fmaxf(fmaxf(fabsf(v[i].x), fabsf(v[i].y)),
                                 fmaxf(fabsf(v[i].z), fabsf(v[i].w))));
    }
#pragma unroll
    for (int o = 16; o; o >>= 1) amax = fmaxf(amax, __shfl_xor_sync(0xffffffffu, amax, o));

    __shared__ float red[8];
    __shared__ float s_bcast;
    if ((tid & 31) == 0) red[tid >> 5] = amax;
    __syncthreads();
    if (tid < 8) {
        float a = red[tid];
#pragma unroll
        for (int o = 4; o; o >>= 1) a = fmaxf(a, __shfl_xor_sync(0xffu, a, o));
        // IEEE ops to bit-match jnp: max(absmax,1e-8)/127
        if (tid == 0) s_bcast = __fdiv_rn(fmaxf(a, 1e-8f), 127.0f);
    }
    __syncthreads();
    const float s = s_bcast;

    __nv_bfloat16* q = isW ? g_qw : g_qx;
    float* sc = isW ? g_sw : g_sx;
    if (tid == 0) sc[row] = s;

    // quantized values are integers in [-127,127]: exact in bf16
    __nv_bfloat162* qp = reinterpret_cast<__nv_bfloat162*>(q + (size_t)row * DIN);
#pragma unroll
    for (int i = 0; i < 4; i++) {
        float4 t = v[i];
        // __fdiv_rn + rintf (round-half-even) matches jnp.round(a/scale) exactly
        float q0 = fminf(fmaxf(rintf(__fdiv_rn(t.x, s)), -127.f), 127.f);
        float q1 = fminf(fmaxf(rintf(__fdiv_rn(t.y, s)), -127.f), 127.f);
        float q2 = fminf(fmaxf(rintf(__fdiv_rn(t.z, s)), -127.f), 127.f);
        float q3 = fminf(fmaxf(rintf(__fdiv_rn(t.w, s)), -127.f), 127.f);
        const int p = tid * 8 + i * 2;
        qp[p]     = __floats2bfloat162_rn(q0, q1);
        qp[p + 1] = __floats2bfloat162_rn(q2, q3);
    }
}

// ---------------- GEMM: out[t,o] = (qx . qw) * sx[t]*sw[o] + bias[o] -----------
// 8 warps as 2(m) x 4(n); warp tile 64x64; mma m16n8k16 bf16 -> f32.
// Fragment double-buffering across k16 steps; B loaded via x4 ldmatrix pairs.
__global__ void __launch_bounds__(256, 1)
gemm_kernel(const float* __restrict__ bias, float* __restrict__ out) {
    extern __shared__ char smem[];
    const uint32_t sb = smem_u32(smem);
    const int tid = threadIdx.x;
    const int wid = tid >> 5;
    const int L   = tid & 31;
    const int bm  = blockIdx.x;   // 64
    const int bn  = blockIdx.y;   // 16

    // stage dequant vectors for this BN slab
    ((float*)(smem + SM_SW))[tid]   = g_sw[bn * BN + tid];
    ((float*)(smem + SM_BIAS))[tid] = bias[bn * BN + tid];

    const __nv_bfloat16* gA = g_qx + (size_t)bm * BM * DIN;
    const __nv_bfloat16* gB = g_qw + (size_t)bn * BN * DIN;

    // per-stage fill: A 4 chunks/thread, B 8 chunks/thread (16B each)
    auto load_stage = [&](int kt, int slot) {
        uint32_t ab = sb + SM_ST0 + slot * STAGE_BYTES;
        uint32_t bb = ab + A_BYTES;
        const __nv_bfloat16* aT = gA + kt * BK;
        const __nv_bfloat16* bT = gB + kt * BK;
#pragma unroll
        for (int i = 0; i < 4; i++) {
            int c = tid + i * 256;
            int row = c >> 3, ko = c & 7;
            uint32_t off = row * 128 + ((ko * 16) ^ ((row & 7) * 16));   // SW128
            CP16(ab + off, aT + (size_t)row * DIN + ko * 8);
        }
#pragma unroll
        for (int i = 0; i < 8; i++) {
            int c = tid + i * 256;
            int row = c >> 3, ko = c & 7;
            uint32_t off = row * 128 + ((ko * 16) ^ ((row & 7) * 16));
            CP16(bb + off, bT + (size_t)row * DIN + ko * 8);
        }
    };

    // warp layout + per-lane ldmatrix address constants
    const int wm = wid >> 2;             // 0..1 -> 64 M rows
    const int wn = wid & 3;              // 0..3 -> 64 N cols
    const int lr = L & 7;
    const int cRow = lr * 16;            // swizzle XOR term ((row&7)*16)
    const int akh = ((L >> 4) & 1) * 16; // A k-half select (matrices 2,3)
    const int bkh = ((L >> 3) & 1) * 16; // B k-half select (matrices 1,3)

    uint32_t aRow[4], bRowP[4];
#pragma unroll
    for (int mf = 0; mf < 4; mf++)
        aRow[mf] = (uint32_t)(wm * 64 + mf * 16 + lr + ((L >> 3) & 1) * 8) * 128;
    // B x4 pairing: lanes 0-15 -> n8 block 2p (k lo/hi), lanes 16-31 -> block 2p+1
#pragma unroll
    for (int p = 0; p < 4; p++)
        bRowP[p] = (uint32_t)(wn * 64 + p * 16 + ((L >> 4) & 1) * 8 + lr) * 128;

    float acc[4][8][4];
#pragma unroll
    for (int mf = 0; mf < 4; mf++)
#pragma unroll
        for (int nf = 0; nf < 8; nf++)
#pragma unroll
            for (int j = 0; j < 4; j++) acc[mf][nf][j] = 0.f;

    // prologue: fill stages 0..STAGES-2
#pragma unroll
    for (int p = 0; p < STAGES - 1; ++p) {
        load_stage(p, p);
        CP_COMMIT();
    }

    uint32_t afr[2][4][4], bfr[2][4][4];   // double-buffered fragments

#pragma unroll 1
    for (int it = 0; it < NIT; ++it) {
        CP_WAIT1();          // stage `it` resident
        __syncthreads();     // all warps done with compute(it-1) before its slot refills

        const int jf = it + STAGES - 1;
        if (jf < NIT) load_stage(jf, jf % STAGES);
        CP_COMMIT();         // uniform group count (empty near tail)

        const uint32_t ab = sb + SM_ST0 + (it % STAGES) * STAGE_BYTES;
        const uint32_t bb = ab + A_BYTES;

        // prefetch ks=0 fragments
#pragma unroll
        for (int mf = 0; mf < 4; mf++)
            LDSM4(afr[0][mf], ab + aRow[mf] + (akh ^ cRow));
#pragma unroll
        for (int p = 0; p < 4; p++)
            LDSM4(bfr[0][p], bb + bRowP[p] + (bkh ^ cRow));

#pragma unroll
        for (int ks = 0; ks < 4; ks++) {
            const int cur = ks & 1, nxt = cur ^ 1;
            if (ks < 3) {
                const int kb = (ks + 1) * 32;          // k16 bf16 = 32 bytes
#pragma unroll
                for (int mf = 0; mf < 4; mf++)
                    LDSM4(afr[nxt][mf], ab + aRow[mf] + ((kb + akh) ^ cRow));
#pragma unroll
                for (int p = 0; p < 4; p++)
                    LDSM4(bfr[nxt][p], bb + bRowP[p] + ((kb + bkh) ^ cRow));
            }
#pragma unroll
            for (int mf = 0; mf < 4; mf++)
#pragma unroll
                for (int p = 0; p < 4; p++) {
                    HMMA(acc[mf][2 * p],     afr[cur][mf], bfr[cur][p][0], bfr[cur][p][1]);
                    HMMA(acc[mf][2 * p + 1], afr[cur][mf], bfr[cur][p][2], bfr[cur][p][3]);
                }
        }
    }

    // epilogue: dequant + bias, direct float2 stores
    const int qid = L >> 2;
    const int tc  = (L & 3) * 2;
    const float* swp = (const float*)(smem + SM_SW);
    const float* bp  = (const float*)(smem + SM_BIAS);

#pragma unroll
    for (int mf = 0; mf < 4; mf++) {
        const size_t gr0 = (size_t)bm * BM + wm * 64 + mf * 16 + qid;
        const float sx0 = g_sx[gr0];
        const float sx1 = g_sx[gr0 + 8];
        float* o0 = out + gr0 * DOUT + bn * BN;
        float* o1 = o0 + (size_t)8 * DOUT;
#pragma unroll
        for (int nf = 0; nf < 8; nf++) {
            const int col = wn * 64 + nf * 8 + tc;
            const float w0 = swp[col], w1 = swp[col + 1];
            const float b0 = bp[col],  b1 = bp[col + 1];
            float2 v0, v1;
            v0.x = acc[mf][nf][0] * (sx0 * w0) + b0;
            v0.y = acc[mf][nf][1] * (sx0 * w1) + b1;
            v1.x = acc[mf][nf][2] * (sx1 * w0) + b0;
            v1.y = acc[mf][nf][3] * (sx1 * w1) + b1;
            *reinterpret_cast<float2*>(o0 + col) = v0;
            *reinterpret_cast<float2*>(o1 + col) = v1;
        }
    }
}

// ---------------- launch ----------------
extern "C" void kernel_launch(void* const* d_in, const int* in_sizes, int n_in,
                              void* d_out, int out_size) {
    const float* x    = (const float*)d_in[0];
    const float* W    = (const float*)d_in[1];
    const float* bias = (const float*)d_in[2];
    float* out        = (float*)d_out;

    quant_kernel<<<TOKENS + DOUT, 256>>>(x, W);

    cudaFuncSetAttribute(gemm_kernel, cudaFuncAttributeMaxDynamicSharedMemorySize, SMEM_TOTAL);
    dim3 grid(TOKENS / BM, DOUT / BN);
    gemm_kernel<<<grid, 256, SMEM_TOTAL>>>(bias, out);
}

// round 10
// speedup vs baseline: 3.1834x; 1.1646x over previous
#include <cuda_runtime.h>
#include <cuda_bf16.h>
#include <cstdint>

// Problem shapes (fixed for this dataset)
#define TOKENS 8192
#define DIN    4096
#define DOUT   4096

// GEMM tiling (bf16 HMMA path, baseline PTX only: cp.async + ldmatrix + mma.sync)
#define BM 128
#define BN 256
#define BK 64                        // 64 bf16 = one 128B SW128 row
#define STAGES 4
#define NIT (DIN / BK)               // 64 K-iterations

#define A_BYTES (BM * 128)           // 16384
#define B_BYTES (BN * 128)           // 32768
#define STAGE_BYTES (A_BYTES + B_BYTES)  // 49152

// SMEM layout (dynamic)
#define SM_SW   0                    // 256 floats
#define SM_BIAS 1024                 // 256 floats
#define SM_ST0  2048
#define SMEM_TOTAL (SM_ST0 + STAGES * STAGE_BYTES)   // 198656

// ---------------- device-global scratch (no allocation allowed) ----------------
__device__ __align__(256) __nv_bfloat16 g_qx[(size_t)TOKENS * DIN];
__device__ __align__(256) __nv_bfloat16 g_qw[(size_t)DOUT * DIN];
__device__ float g_sx[TOKENS];
__device__ float g_sw[DOUT];

// ---------------- PTX helpers (all baseline, compile under compute_103) --------
__device__ __forceinline__ uint32_t smem_u32(const void* p) {
    uint32_t a;
    asm("{ .reg .u64 t; cvta.to.shared.u64 t, %1; cvt.u32.u64 %0, t; }" : "=r"(a) : "l"(p));
    return a;
}

#define CP16(dst, src) \
    asm volatile("cp.async.cg.shared.global [%0], [%1], 16;\n" \
                 :: "r"(dst), "l"(__cvta_generic_to_global(src)))
#define CP_COMMIT() asm volatile("cp.async.commit_group;\n" ::: "memory")
#define CP_WAIT2()  asm volatile("cp.async.wait_group 2;\n" ::: "memory")

#define LDSM4(r, addr) \
    asm volatile("ldmatrix.sync.aligned.m8n8.x4.shared.b16 {%0,%1,%2,%3}, [%4];" \
                 : "=r"((r)[0]), "=r"((r)[1]), "=r"((r)[2]), "=r"((r)[3]) : "r"(addr))

// bf16 x bf16 -> f32 accumulate (HMMA hardware fallback path on sm_103)
#define HMMA(d, a, b0, b1) \
    asm volatile("mma.sync.aligned.m16n8k16.row.col.f32.bf16.bf16.f32 " \
                 "{%0,%1,%2,%3}, {%4,%5,%6,%7}, {%8,%9}, {%0,%1,%2,%3};" \
                 : "+f"((d)[0]), "+f"((d)[1]), "+f"((d)[2]), "+f"((d)[3]) \
                 : "r"((a)[0]), "r"((a)[1]), "r"((a)[2]), "r"((a)[3]), \
                   "r"(b0), "r"(b1))

// ---------------- quantize (fused x + W): per-row absmax -> bf16 ints + scale --
// grid = TOKENS + DOUT; 256 threads/row; thread t owns 16 consecutive floats.
__global__ void __launch_bounds__(256) quant_kernel(const float* __restrict__ x,
                                                    const float* __restrict__ W) {
    const int blk = blockIdx.x;
    const bool isW = (blk >= TOKENS);
    const int row = isW ? (blk - TOKENS) : blk;
    const float* in = isW ? W : x;
    const int tid = threadIdx.x;
    const float4* inr = reinterpret_cast<const float4*>(in + (size_t)row * DIN) + tid * 4;

    float4 v[4];
    float amax = 0.f;
#pragma unroll
    for (int i = 0; i < 4; i++) {
        v[i] = inr[i];
        amax = fmaxf(amax, fmaxf(fmaxf(fabsf(v[i].x), fabsf(v[i].y)),
                                 fmaxf(fabsf(v[i].z), fabsf(v[i].w))));
    }
#pragma unroll
    for (int o = 16; o; o >>= 1) amax = fmaxf(amax, __shfl_xor_sync(0xffffffffu, amax, o));

    __shared__ float red[8];
    __shared__ float s_bcast;
    if ((tid & 31) == 0) red[tid >> 5] = amax;
    __syncthreads();
    if (tid < 8) {
        float a = red[tid];
#pragma unroll
        for (int o = 4; o; o >>= 1) a = fmaxf(a, __shfl_xor_sync(0xffu, a, o));
        // IEEE ops to bit-match jnp: max(absmax,1e-8)/127
        if (tid == 0) s_bcast = __fdiv_rn(fmaxf(a, 1e-8f), 127.0f);
    }
    __syncthreads();
    const float s = s_bcast;

    __nv_bfloat16* q = isW ? g_qw : g_qx;
    float* sc = isW ? g_sw : g_sx;
    if (tid == 0) sc[row] = s;

    // quantized values are integers in [-127,127]: exact in bf16
    __nv_bfloat162* qp = reinterpret_cast<__nv_bfloat162*>(q + (size_t)row * DIN);
#pragma unroll
    for (int i = 0; i < 4; i++) {
        float4 t = v[i];
        // __fdiv_rn + rintf (round-half-even) matches jnp.round(a/scale) exactly
        float q0 = fminf(fmaxf(rintf(__fdiv_rn(t.x, s)), -127.f), 127.f);
        float q1 = fminf(fmaxf(rintf(__fdiv_rn(t.y, s)), -127.f), 127.f);
        float q2 = fminf(fmaxf(rintf(__fdiv_rn(t.z, s)), -127.f), 127.f);
        float q3 = fminf(fmaxf(rintf(__fdiv_rn(t.w, s)), -127.f), 127.f);
        const int p = tid * 8 + i * 2;
        qp[p]     = __floats2bfloat162_rn(q0, q1);
        qp[p + 1] = __floats2bfloat162_rn(q2, q3);
    }
}

// ---------------- GEMM: out[t,o] = (qx . qw) * sx[t]*sw[o] + bias[o] -----------
// 8 warps as 2(m) x 4(n); warp tile 64x64; mma m16n8k16 bf16 -> f32.
// 4-stage cp.async ring; fragment pipeline carried ACROSS iteration boundaries:
// at ks=3 of iteration it we prefetch (it+1, ks=0) fragments from stage
// (it+1)%4 — resident per cp.async.wait_group 2 (two stages complete), and that
// slot is not rewritten until iteration it+2 (guarded by the head barrier).
__global__ void __launch_bounds__(256, 1)
gemm_kernel(const float* __restrict__ bias, float* __restrict__ out) {
    extern __shared__ char smem[];
    const uint32_t sb = smem_u32(smem);
    const int tid = threadIdx.x;
    const int wid = tid >> 5;
    const int L   = tid & 31;
    const int bm  = blockIdx.x;   // 64
    const int bn  = blockIdx.y;   // 16

    // stage dequant vectors for this BN slab
    ((float*)(smem + SM_SW))[tid]   = g_sw[bn * BN + tid];
    ((float*)(smem + SM_BIAS))[tid] = bias[bn * BN + tid];

    const __nv_bfloat16* gA = g_qx + (size_t)bm * BM * DIN;
    const __nv_bfloat16* gB = g_qw + (size_t)bn * BN * DIN;

    // per-stage fill: A 4 chunks/thread, B 8 chunks/thread (16B each)
    auto load_stage = [&](int kt, int slot) {
        uint32_t ab = sb + SM_ST0 + slot * STAGE_BYTES;
        uint32_t bb = ab + A_BYTES;
        const __nv_bfloat16* aT = gA + kt * BK;
        const __nv_bfloat16* bT = gB + kt * BK;
#pragma unroll
        for (int i = 0; i < 4; i++) {
            int c = tid + i * 256;
            int row = c >> 3, ko = c & 7;
            uint32_t off = row * 128 + ((ko * 16) ^ ((row & 7) * 16));   // SW128
            CP16(ab + off, aT + (size_t)row * DIN + ko * 8);
        }
#pragma unroll
        for (int i = 0; i < 8; i++) {
            int c = tid + i * 256;
            int row = c >> 3, ko = c & 7;
            uint32_t off = row * 128 + ((ko * 16) ^ ((row & 7) * 16));
            CP16(bb + off, bT + (size_t)row * DIN + ko * 8);
        }
    };

    // warp layout + per-lane ldmatrix address constants
    const int wm = wid >> 2;             // 0..1 -> 64 M rows
    const int wn = wid & 3;              // 0..3 -> 64 N cols
    const int lr = L & 7;
    const int cRow = lr * 16;            // swizzle XOR term ((row&7)*16)
    const int akh = ((L >> 4) & 1) * 16; // A k-half select (matrices 2,3)
    const int bkh = ((L >> 3) & 1) * 16; // B k-half select (matrices 1,3)

    uint32_t aRow[4], bRowP[4];
#pragma unroll
    for (int mf = 0; mf < 4; mf++)
        aRow[mf] = (uint32_t)(wm * 64 + mf * 16 + lr + ((L >> 3) & 1) * 8) * 128;
    // B x4 pairing: lanes 0-15 -> n8 block 2p (k lo/hi), lanes 16-31 -> block 2p+1
#pragma unroll
    for (int p = 0; p < 4; p++)
        bRowP[p] = (uint32_t)(wn * 64 + p * 16 + ((L >> 4) & 1) * 8 + lr) * 128;

    float acc[4][8][4];
#pragma unroll
    for (int mf = 0; mf < 4; mf++)
#pragma unroll
        for (int nf = 0; nf < 8; nf++)
#pragma unroll
            for (int j = 0; j < 4; j++) acc[mf][nf][j] = 0.f;

    // prologue: fill stages 0..2, ensure stage 0 resident, prefetch its ks=0 frags
#pragma unroll
    for (int p = 0; p < STAGES - 1; ++p) {
        load_stage(p, p);
        CP_COMMIT();
    }
    CP_WAIT2();          // <=2 pending -> group 0 complete
    __syncthreads();

    uint32_t afr[2][4][4], bfr[2][4][4];   // double-buffered fragments
    {
        const uint32_t ab0 = sb + SM_ST0;
        const uint32_t bb0 = ab0 + A_BYTES;
#pragma unroll
        for (int mf = 0; mf < 4; mf++)
            LDSM4(afr[0][mf], ab0 + aRow[mf] + (akh ^ cRow));
#pragma unroll
        for (int p = 0; p < 4; p++)
            LDSM4(bfr[0][p], bb0 + bRowP[p] + (bkh ^ cRow));
    }

#pragma unroll 1
    for (int it = 0; it < NIT; ++it) {
        __syncthreads();     // guard: slot (it+3)%4 refill vs its readers in it-1

        const int jf = it + STAGES - 1;
        if (jf < NIT) load_stage(jf, jf % STAGES);
        CP_COMMIT();         // uniform group count (empty near tail)
        CP_WAIT2();          // stages it and it+1 resident

        const uint32_t ab  = sb + SM_ST0 + (it % STAGES) * STAGE_BYTES;
        const uint32_t bb  = ab + A_BYTES;
        const uint32_t abn = sb + SM_ST0 + ((it + 1) % STAGES) * STAGE_BYTES;
        const uint32_t bbn = abn + A_BYTES;

#pragma unroll
        for (int ks = 0; ks < 4; ks++) {
            const int cur = ks & 1, nxt = cur ^ 1;
            if (ks < 3) {
                const int kb = (ks + 1) * 32;          // k16 bf16 = 32 bytes
#pragma unroll
                for (int mf = 0; mf < 4; mf++)
                    LDSM4(afr[nxt][mf], ab + aRow[mf] + ((kb + akh) ^ cRow));
#pragma unroll
                for (int p = 0; p < 4; p++)
                    LDSM4(bfr[nxt][p], bb + bRowP[p] + ((kb + bkh) ^ cRow));
            } else if (it + 1 < NIT) {
                // cross-iteration prefetch: (it+1, ks=0) from stage (it+1)%4
#pragma unroll
                for (int mf = 0; mf < 4; mf++)
                    LDSM4(afr[nxt][mf], abn + aRow[mf] + (akh ^ cRow));
#pragma unroll
                for (int p = 0; p < 4; p++)
                    LDSM4(bfr[nxt][p], bbn + bRowP[p] + (bkh ^ cRow));
            }
#pragma unroll
            for (int mf = 0; mf < 4; mf++)
#pragma unroll
                for (int p = 0; p < 4; p++) {
                    HMMA(acc[mf][2 * p],     afr[cur][mf], bfr[cur][p][0], bfr[cur][p][1]);
                    HMMA(acc[mf][2 * p + 1], afr[cur][mf], bfr[cur][p][2], bfr[cur][p][3]);
                }
        }
    }

    // epilogue: dequant + bias, direct float2 stores
    const int qid = L >> 2;
    const int tc  = (L & 3) * 2;
    const float* swp = (const float*)(smem + SM_SW);
    const float* bp  = (const float*)(smem + SM_BIAS);

#pragma unroll
    for (int mf = 0; mf < 4; mf++) {
        const size_t gr0 = (size_t)bm * BM + wm * 64 + mf * 16 + qid;
        const float sx0 = g_sx[gr0];
        const float sx1 = g_sx[gr0 + 8];
        float* o0 = out + gr0 * DOUT + bn * BN;
        float* o1 = o0 + (size_t)8 * DOUT;
#pragma unroll
        for (int nf = 0; nf < 8; nf++) {
            const int col = wn * 64 + nf * 8 + tc;
            const float w0 = swp[col], w1 = swp[col + 1];
            const float b0 = bp[col],  b1 = bp[col + 1];
            float2 v0, v1;
            v0.x = acc[mf][nf][0] * (sx0 * w0) + b0;
            v0.y = acc[mf][nf][1] * (sx0 * w1) + b1;
            v1.x = acc[mf][nf][2] * (sx1 * w0) + b0;
            v1.y = acc[mf][nf][3] * (sx1 * w1) + b1;
            *reinterpret_cast<float2*>(o0 + col) = v0;
            *reinterpret_cast<float2*>(o1 + col) = v1;
        }
    }
}

// ---------------- launch ----------------
extern "C" void kernel_launch(void* const* d_in, const int* in_sizes, int n_in,
                              void* d_out, int out_size) {
    const float* x    = (const float*)d_in[0];
    const float* W    = (const float*)d_in[1];
    const float* bias = (const float*)d_in[2];
    float* out        = (float*)d_out;

    quant_kernel<<<TOKENS + DOUT, 256>>>(x, W);

    cudaFuncSetAttribute(gemm_kernel, cudaFuncAttributeMaxDynamicSharedMemorySize, SMEM_TOTAL);
    dim3 grid(TOKENS / BM, DOUT / BN);
    gemm_kernel<<<grid, 256, SMEM_TOTAL>>>(bias, out);
}